// round 14
// baseline (speedup 1.0000x reference)
#include <cuda_runtime.h>
#include <cuda_fp16.h>
#include <cstdint>

#define BB  4
#define SS  2048
#define DD  1024
#define HH  16
#define DKK 64
#define NN  (BB*SS)
#define NND (NN*DD)
#define WSZ (DD*DD)

// ---- fp16x3 warp-MMA GEMM tiling ----
#define BM   128
#define BN   128
#define BK   32
#define NIT  (DD/BK)            // 32
#define RS   20
#define PLANE (BM*RS)
#define STAGEF (4*PLANE)
#define GEMM_SMEM (2*STAGEF*4)  // 81920 bytes

// ---- attention tiling ----
#define TQ   128
#define TKV  64
#define K36  36
#define KVW  (64*K36)
#define BUFW (4*KVW)
#define PSW  (2*BUFW)
#define ATTN_SMEM ((2*BUFW + 128*K36)*4)   // 92160 bytes

// scratch
__device__ __half g_wh[4*WSZ];    // weights hi: Wq^T,Wk^T,Wv^T (K-major), Wo
__device__ __half g_wl[4*WSZ];
__device__ __half g_xh[3*NND];    // q/k/v hi planes [B,S,H,DK]
__device__ __half g_xl[3*NND];
__device__ __half g_ch[NND];      // concat hi/lo planes [B,S,D]
__device__ __half g_cl[NND];

__device__ __forceinline__ uint32_t smem_u32(const void* p) {
    uint32_t a;
    asm("{ .reg .u64 t; cvta.to.shared.u64 t, %1; cvt.u32.u64 %0, t; }" : "=r"(a) : "l"(p));
    return a;
}
__device__ __forceinline__ void ldm4(uint32_t* r, uint32_t a) {
    asm volatile("ldmatrix.sync.aligned.m8n8.x4.shared.b16 {%0,%1,%2,%3}, [%4];"
        : "=r"(r[0]), "=r"(r[1]), "=r"(r[2]), "=r"(r[3]) : "r"(a));
}

__device__ __forceinline__ void split8(float4 p, float4 q, uint4& hi, uint4& lo) {
    __half2 h0 = __floats2half2_rn(p.x, p.y);
    __half2 h1 = __floats2half2_rn(p.z, p.w);
    __half2 h2v = __floats2half2_rn(q.x, q.y);
    __half2 h3 = __floats2half2_rn(q.z, q.w);
    float2 f0 = __half22float2(h0), f1 = __half22float2(h1);
    float2 f2 = __half22float2(h2v), f3 = __half22float2(h3);
    __half2 l0 = __floats2half2_rn(p.x - f0.x, p.y - f0.y);
    __half2 l1 = __floats2half2_rn(p.z - f1.x, p.w - f1.y);
    __half2 l2 = __floats2half2_rn(q.x - f2.x, q.y - f2.y);
    __half2 l3 = __floats2half2_rn(q.z - f3.x, q.w - f3.y);
    hi = make_uint4(*(uint32_t*)&h0, *(uint32_t*)&h1, *(uint32_t*)&h2v, *(uint32_t*)&h3);
    lo = make_uint4(*(uint32_t*)&l0, *(uint32_t*)&l1, *(uint32_t*)&l2, *(uint32_t*)&l3);
}

__device__ __forceinline__ void mma16(float* d, const uint32_t* a, uint32_t b0, uint32_t b1) {
    asm volatile("mma.sync.aligned.m16n8k16.row.col.f32.f16.f16.f32 "
        "{%0,%1,%2,%3},{%4,%5,%6,%7},{%8,%9},{%0,%1,%2,%3};"
        : "+f"(d[0]), "+f"(d[1]), "+f"(d[2]), "+f"(d[3])
        : "r"(a[0]), "r"(a[1]), "r"(a[2]), "r"(a[3]), "r"(b0), "r"(b1));
}

// ---------------------------------------------------------------------------
// Weight transpose + fp16 split: Wh/Wl[h*64+dk][d] = split(W[h][d][dk])
// ---------------------------------------------------------------------------
__global__ void transpose_split_w(const float* __restrict__ W,
                                  __half* __restrict__ Wh, __half* __restrict__ Wl)
{
    __shared__ float t[32][33];
    const int h  = blockIdx.z;
    const int d0 = blockIdx.y << 5;
    const int k0 = blockIdx.x << 5;
    const int c  = threadIdx.x & 31;
    const int r4 = threadIdx.x >> 5;
    const float* Whp = W + ((size_t)h << 16);
    #pragma unroll
    for (int i = 0; i < 4; i++)
        t[r4 + 8*i][c] = Whp[(size_t)(d0 + r4 + 8*i) * DKK + k0 + c];
    __syncthreads();
    const size_t ob = (size_t)(h * DKK + k0) * DD + d0;
    #pragma unroll
    for (int i = 0; i < 4; i++) {
        float v = t[c][r4 + 8*i];
        __half hv = __float2half_rn(v);
        __half lv = __float2half_rn(v - __half2float(hv));
        Wh[ob + (size_t)(r4 + 8*i) * DD + c] = hv;
        Wl[ob + (size_t)(r4 + 8*i) * DD + c] = lv;
    }
}

// ---------------------------------------------------------------------------
// split fp32 array into fp16 hi/lo planes (8 floats per thread)
// ---------------------------------------------------------------------------
__global__ void split_half(const float4* __restrict__ X, uint4* __restrict__ hi,
                           uint4* __restrict__ lo, int n8)
{
    int i = blockIdx.x * blockDim.x + threadIdx.x;
    if (i < n8) {
        uint4 h, l;
        split8(X[2*i], X[2*i+1], h, l);
        hi[i] = h; lo[i] = l;
    }
}

// ---------------------------------------------------------------------------
// fp16x3 warp-MMA GEMM.  B always pre-split fp16 planes (direct copy).
// AMODE 0: A fp32 (split in loader).  AMODE 1: A pre-split fp16 planes.
// Epilogue: Cf!=nullptr -> fp32+bias; else fp16 hi/lo planes (seg-selected).
// ---------------------------------------------------------------------------
template<int AMODE>
__global__ __launch_bounds__(256, 1)
void gemm_fp16(const float* __restrict__ A0, const float* __restrict__ A1,
               const float* __restrict__ A2,
               const __half* __restrict__ Ahp, const __half* __restrict__ Alp,
               const __half* __restrict__ Bh, const __half* __restrict__ Bl,
               const float* __restrict__ bias,
               float* __restrict__ Cf, __half* __restrict__ Hhb, __half* __restrict__ Hlb)
{
    extern __shared__ float sm[];
    const uint32_t smb = smem_u32(sm);
    const int tid  = threadIdx.x;
    const int m0   = blockIdx.y * BM;
    const int n0g  = blockIdx.x * BN;
    const int seg  = n0g >> 10;
    const int n0   = n0g & (DD - 1);
    const float* A = (seg == 0) ? A0 : (seg == 1) ? A1 : A2;

    const int w    = tid >> 5, lane = tid & 31;
    const int grp  = lane >> 2, tig = lane & 3;
    const int m_off = (w >> 2) * 64;
    const int n_off = (w & 3) * 32;

    const int a_row = lane & 15;
    const int a_k   = (lane >> 4) * 4;
    const int b_row = (lane & 7) + ((lane >> 1) & 8);
    const int b_k   = ((lane >> 3) & 1) * 4;

    // loader: thread -> (row, half-row of 16 elems)
    const int lrow = tid >> 1, lh = tid & 1;

    float acc[4][4][4];
    #pragma unroll
    for (int t = 0; t < 4; t++)
        #pragma unroll
        for (int u = 0; u < 4; u++)
            #pragma unroll
            for (int q = 0; q < 4; q++) acc[t][u][q] = 0.f;

    float4 raf[4];
    uint4  rah[2], ral[2];
    uint4  rbh[2], rbl[2];

    #define PREFETCH(kk0)                                                          \
    {                                                                              \
        if (AMODE == 0) {                                                          \
            const float* ap = A + (size_t)(m0 + lrow) * DD + (kk0) + lh * 16;      \
            raf[0] = *reinterpret_cast<const float4*>(ap);                         \
            raf[1] = *reinterpret_cast<const float4*>(ap + 4);                     \
            raf[2] = *reinterpret_cast<const float4*>(ap + 8);                     \
            raf[3] = *reinterpret_cast<const float4*>(ap + 12);                    \
        } else {                                                                   \
            const __half* aph = Ahp + (size_t)(m0 + lrow) * DD + (kk0) + lh * 16;  \
            const __half* apl = Alp + (size_t)(m0 + lrow) * DD + (kk0) + lh * 16;  \
            rah[0] = *reinterpret_cast<const uint4*>(aph);                         \
            rah[1] = *reinterpret_cast<const uint4*>(aph + 8);                     \
            ral[0] = *reinterpret_cast<const uint4*>(apl);                         \
            ral[1] = *reinterpret_cast<const uint4*>(apl + 8);                     \
        }                                                                          \
        const __half* bph = Bh + (size_t)(n0g + lrow) * DD + (kk0) + lh * 16;      \
        const __half* bpl = Bl + (size_t)(n0g + lrow) * DD + (kk0) + lh * 16;      \
        rbh[0] = *reinterpret_cast<const uint4*>(bph);                             \
        rbh[1] = *reinterpret_cast<const uint4*>(bph + 8);                         \
        rbl[0] = *reinterpret_cast<const uint4*>(bpl);                             \
        rbl[1] = *reinterpret_cast<const uint4*>(bpl + 8);                         \
    }

    #define STORE_STAGE(stage)                                                     \
    {                                                                              \
        float* AHI = sm + (stage) * STAGEF;                                        \
        float* ALO = AHI + PLANE;                                                  \
        float* BHI = AHI + 2 * PLANE;                                              \
        float* BLO = AHI + 3 * PLANE;                                              \
        const int wo = lrow * RS + lh * 8;                                         \
        if (AMODE == 0) {                                                          \
            uint4 h0, l0, h1, l1;                                                  \
            split8(raf[0], raf[1], h0, l0);                                        \
            split8(raf[2], raf[3], h1, l1);                                        \
            *reinterpret_cast<uint4*>(AHI + wo)     = h0;                          \
            *reinterpret_cast<uint4*>(AHI + wo + 4) = h1;                          \
            *reinterpret_cast<uint4*>(ALO + wo)     = l0;                          \
            *reinterpret_cast<uint4*>(ALO + wo + 4) = l1;                          \
        } else {                                                                   \
            *reinterpret_cast<uint4*>(AHI + wo)     = rah[0];                      \
            *reinterpret_cast<uint4*>(AHI + wo + 4) = rah[1];                      \
            *reinterpret_cast<uint4*>(ALO + wo)     = ral[0];                      \
            *reinterpret_cast<uint4*>(ALO + wo + 4) = ral[1];                      \
        }                                                                          \
        *reinterpret_cast<uint4*>(BHI + wo)     = rbh[0];                          \
        *reinterpret_cast<uint4*>(BHI + wo + 4) = rbh[1];                          \
        *reinterpret_cast<uint4*>(BLO + wo)     = rbl[0];                          \
        *reinterpret_cast<uint4*>(BLO + wo + 4) = rbl[1];                          \
    }

    PREFETCH(0);
    STORE_STAGE(0);
    __syncthreads();

    for (int c = 0; c < NIT; ++c) {
        if (c + 1 < NIT) PREFETCH((c + 1) * BK);

        const uint32_t sbase = smb + (uint32_t)(c & 1) * (STAGEF * 4u);

        #pragma unroll
        for (int s = 0; s < 2; ++s) {
            uint32_t ah[4][4], al[4][4];
            #pragma unroll
            for (int t = 0; t < 4; t++) {
                const uint32_t offA = (uint32_t)((m_off + t*16 + a_row) * RS + s*8 + a_k) * 4u;
                ldm4(ah[t], sbase + offA);
                ldm4(al[t], sbase + PLANE*4u + offA);
            }
            uint32_t bh[2][4], bl[2][4];
            #pragma unroll
            for (int u2 = 0; u2 < 2; u2++) {
                const uint32_t offB = (uint32_t)((n_off + u2*16 + b_row) * RS + s*8 + b_k) * 4u;
                ldm4(bh[u2], sbase + 2u*PLANE*4u + offB);
                ldm4(bl[u2], sbase + 3u*PLANE*4u + offB);
            }
            #pragma unroll
            for (int u2 = 0; u2 < 2; u2++)
                #pragma unroll
                for (int p = 0; p < 2; p++) {
                    const int u = u2 * 2 + p;
                    #pragma unroll
                    for (int t = 0; t < 4; t++) {
                        mma16(acc[t][u], ah[t], bh[u2][2*p], bh[u2][2*p+1]);
                        mma16(acc[t][u], ah[t], bl[u2][2*p], bl[u2][2*p+1]);
                        mma16(acc[t][u], al[t], bh[u2][2*p], bh[u2][2*p+1]);
                    }
                }
        }

        if (c + 1 < NIT) STORE_STAGE((c + 1) & 1);
        __syncthreads();
    }
    #undef PREFETCH
    #undef STORE_STAGE

    if (Cf != nullptr) {
        #pragma unroll
        for (int u = 0; u < 4; u++) {
            const int ncol = n0 + n_off + u * 8 + tig * 2;
            float2 bv = *reinterpret_cast<const float2*>(bias + ncol);
            #pragma unroll
            for (int t = 0; t < 4; t++) {
                const int r = m0 + m_off + t * 16 + grp;
                *reinterpret_cast<float2*>(Cf + (size_t)r * DD + ncol) =
                    make_float2(acc[t][u][0] + bv.x, acc[t][u][1] + bv.y);
                *reinterpret_cast<float2*>(Cf + (size_t)(r + 8) * DD + ncol) =
                    make_float2(acc[t][u][2] + bv.x, acc[t][u][3] + bv.y);
            }
        }
    } else {
        __half* Hh = Hhb + (size_t)seg * NND;
        __half* Hl = Hlb + (size_t)seg * NND;
        #pragma unroll
        for (int u = 0; u < 4; u++) {
            const int ncol = n0 + n_off + u * 8 + tig * 2;
            #pragma unroll
            for (int t = 0; t < 4; t++) {
                const int r = m0 + m_off + t * 16 + grp;
                __half2 h0 = __floats2half2_rn(acc[t][u][0], acc[t][u][1]);
                float2  f0 = __half22float2(h0);
                __half2 l0 = __floats2half2_rn(acc[t][u][0] - f0.x, acc[t][u][1] - f0.y);
                *reinterpret_cast<__half2*>(Hh + (size_t)r * DD + ncol) = h0;
                *reinterpret_cast<__half2*>(Hl + (size_t)r * DD + ncol) = l0;
                __half2 h1 = __floats2half2_rn(acc[t][u][2], acc[t][u][3]);
                float2  f1 = __half22float2(h1);
                __half2 l1 = __floats2half2_rn(acc[t][u][2] - f1.x, acc[t][u][3] - f1.y);
                *reinterpret_cast<__half2*>(Hh + (size_t)(r + 8) * DD + ncol) = h1;
                *reinterpret_cast<__half2*>(Hl + (size_t)(r + 8) * DD + ncol) = l1;
            }
        }
    }
}

// ---------------------------------------------------------------------------
// Causal flash attention (round-13, passing): fp16 mma + ldmatrix, fp16 plane
// inputs, double-buffered K/V, one barrier per kv-tile. Epilogue now writes
// concat as fp16 hi/lo planes (same split arithmetic as the old loader).
// ---------------------------------------------------------------------------
__global__ __launch_bounds__(256, 1)
void attn_mma(const __half* __restrict__ qh, const __half* __restrict__ ql,
              const __half* __restrict__ kh, const __half* __restrict__ kl,
              const __half* __restrict__ vh, const __half* __restrict__ vl,
              __half* __restrict__ och, __half* __restrict__ ocl)
{
    extern __shared__ float smf[];
    float* Ps = smf + PSW;
    const uint32_t smb = smem_u32(smf);
    const uint32_t aPs = smb + (uint32_t)PSW * 4u;

    const int tid  = threadIdx.x;
    const int w    = tid >> 5, lane = tid & 31;
    const int grp  = lane >> 2, tig = lane & 3;
    const int wrow = w * 16;
    const int h    = blockIdx.y, b = blockIdx.z;
    const int st   = gridDim.x - 1 - blockIdx.x;
    const int s0   = st * TQ;

    const int a_row = lane & 15;
    const int a_k   = (lane >> 4) * 4;
    const int b_row = (lane & 7) + ((lane >> 1) & 8);
    const int b_k   = ((lane >> 3) & 1) * 4;

    const size_t qoff = ((size_t)b * SS + s0) * DD + h * DKK;
    const size_t koff = (size_t)b * SS * DD + h * DKK;
    const __half* qhb = qh + qoff;
    const __half* qlb = ql + qoff;
    const __half* khb = kh + koff;
    const __half* klb = kl + koff;
    const __half* vhb = vh + koff;
    const __half* vlb = vl + koff;

    const int krow = tid >> 2, kq = (tid & 3) * 8;
    const int vw8  = w * 8;

    uint4 kh_r[2], kl_r[2], vh0_r, vh1_r, vl0_r, vl1_r;
    kh_r[0] = *reinterpret_cast<const uint4*>(khb + (size_t)krow * DD + kq * 2);
    kh_r[1] = *reinterpret_cast<const uint4*>(khb + (size_t)krow * DD + kq * 2 + 8);
    kl_r[0] = *reinterpret_cast<const uint4*>(klb + (size_t)krow * DD + kq * 2);
    kl_r[1] = *reinterpret_cast<const uint4*>(klb + (size_t)krow * DD + kq * 2 + 8);
    vh0_r = *reinterpret_cast<const uint4*>(vhb + (size_t)(2*lane)   * DD + vw8);
    vh1_r = *reinterpret_cast<const uint4*>(vhb + (size_t)(2*lane+1) * DD + vw8);
    vl0_r = *reinterpret_cast<const uint4*>(vlb + (size_t)(2*lane)   * DD + vw8);
    vl1_r = *reinterpret_cast<const uint4*>(vlb + (size_t)(2*lane+1) * DD + vw8);

    #pragma unroll
    for (int u = 0; u < 4; u++) {
        int f = tid + u * 256;
        int row = f >> 3, oct = f & 7;
        *reinterpret_cast<uint4*>(Ps + row * K36 + oct * 4) =
            *reinterpret_cast<const uint4*>(qhb + (size_t)row * DD + oct * 8);
        *reinterpret_cast<uint4*>(smf + row * K36 + oct * 4) =
            *reinterpret_cast<const uint4*>(qlb + (size_t)row * DD + oct * 8);
    }
    __syncthreads();
    uint32_t aqh[4][4], aql[4][4];
    #pragma unroll
    for (int ks = 0; ks < 4; ks++) {
        const uint32_t offQ = (uint32_t)((wrow + a_row) * K36 + ks*8 + a_k) * 4u;
        ldm4(aqh[ks], aPs + offQ);
        ldm4(aql[ks], smb + offQ);
    }
    __syncthreads();

    #define KV_STORE(buf)                                                         \
    {                                                                             \
        float* Kh = smf + (buf) * BUFW;                                           \
        float* Kl = Kh + KVW;                                                     \
        uint32_t* Vh = reinterpret_cast<uint32_t*>(Kh + 2*KVW);                   \
        uint32_t* Vl = reinterpret_cast<uint32_t*>(Kh + 3*KVW);                   \
        *reinterpret_cast<uint4*>(Kh + krow * K36 + kq)     = kh_r[0];            \
        *reinterpret_cast<uint4*>(Kh + krow * K36 + kq + 4) = kh_r[1];            \
        *reinterpret_cast<uint4*>(Kl + krow * K36 + kq)     = kl_r[0];            \
        *reinterpret_cast<uint4*>(Kl + krow * K36 + kq + 4) = kl_r[1];            \
        _Pragma("unroll")                                                         \
        for (int j = 0; j < 8; j++) {                                             \
            const uint32_t sel = (j & 1) ? 0x7632u : 0x5410u;                     \
            Vh[(vw8 + j) * K36 + lane] = __byte_perm(                             \
                (&vh0_r.x)[j >> 1], (&vh1_r.x)[j >> 1], sel);                     \
            Vl[(vw8 + j) * K36 + lane] = __byte_perm(                             \
                (&vl0_r.x)[j >> 1], (&vl1_r.x)[j >> 1], sel);                     \
        }                                                                         \
    }

    KV_STORE(0);
    __syncthreads();

    float m0r = -1e30f, m1r = -1e30f, l0 = 0.f, l1 = 0.f;
    float of[8][4];
    #pragma unroll
    for (int nt = 0; nt < 8; nt++)
        #pragma unroll
        for (int q = 0; q < 4; q++) of[nt][q] = 0.f;

    const int ntiles = s0 / TKV + 2;
    for (int tt = 0; tt < ntiles; ++tt) {
        if (tt + 1 < ntiles) {
            const size_t t0n = (size_t)(tt + 1) * TKV;
            kh_r[0] = *reinterpret_cast<const uint4*>(khb + (t0n + krow) * DD + kq * 2);
            kh_r[1] = *reinterpret_cast<const uint4*>(khb + (t0n + krow) * DD + kq * 2 + 8);
            kl_r[0] = *reinterpret_cast<const uint4*>(klb + (t0n + krow) * DD + kq * 2);
            kl_r[1] = *reinterpret_cast<const uint4*>(klb + (t0n + krow) * DD + kq * 2 + 8);
            vh0_r = *reinterpret_cast<const uint4*>(vhb + (t0n + 2*lane)   * DD + vw8);
            vh1_r = *reinterpret_cast<const uint4*>(vhb + (t0n + 2*lane+1) * DD + vw8);
            vl0_r = *reinterpret_cast<const uint4*>(vlb + (t0n + 2*lane)   * DD + vw8);
            vl1_r = *reinterpret_cast<const uint4*>(vlb + (t0n + 2*lane+1) * DD + vw8);
        }

        const uint32_t aBuf  = smb + (uint32_t)(tt & 1) * (BUFW * 4u);
        const uint32_t aKhi  = aBuf;
        const uint32_t aKlo  = aBuf + KVW * 4u;
        const uint32_t aVthi = aBuf + 2u * KVW * 4u;
        const uint32_t aVtlo = aBuf + 3u * KVW * 4u;

        float sf[8][4];
        #pragma unroll
        for (int nt = 0; nt < 8; nt++)
            #pragma unroll
            for (int q = 0; q < 4; q++) sf[nt][q] = 0.f;

        #pragma unroll
        for (int ks = 0; ks < 4; ks++) {
            #pragma unroll
            for (int nt2 = 0; nt2 < 4; nt2++) {
                const uint32_t offK = (uint32_t)((nt2*16 + b_row) * K36 + ks*8 + b_k) * 4u;
                uint32_t rh[4], rl[4];
                ldm4(rh, aKhi + offK);
                ldm4(rl, aKlo + offK);
                mma16(sf[2*nt2],   aqh[ks], rh[0], rh[1]);
                mma16(sf[2*nt2],   aql[ks], rh[0], rh[1]);
                mma16(sf[2*nt2],   aqh[ks], rl[0], rl[1]);
                mma16(sf[2*nt2+1], aqh[ks], rh[2], rh[3]);
                mma16(sf[2*nt2+1], aql[ks], rh[2], rh[3]);
                mma16(sf[2*nt2+1], aqh[ks], rl[2], rl[3]);
            }
        }

        const int t0 = tt * TKV;
        #pragma unroll
        for (int nt = 0; nt < 8; nt++)
            #pragma unroll
            for (int q = 0; q < 4; q++) sf[nt][q] *= 8.0f;
        if (t0 + TKV > s0) {
            const int r0g = s0 + wrow + grp, r1g = r0g + 8;
            #pragma unroll
            for (int nt = 0; nt < 8; nt++) {
                const int c0g = t0 + nt*8 + 2*tig;
                if (c0g     > r0g) sf[nt][0] = -1e30f;
                if (c0g + 1 > r0g) sf[nt][1] = -1e30f;
                if (c0g     > r1g) sf[nt][2] = -1e30f;
                if (c0g + 1 > r1g) sf[nt][3] = -1e30f;
            }
        }

        float mt0 = -1e30f, mt1 = -1e30f;
        #pragma unroll
        for (int nt = 0; nt < 8; nt++) {
            mt0 = fmaxf(mt0, fmaxf(sf[nt][0], sf[nt][1]));
            mt1 = fmaxf(mt1, fmaxf(sf[nt][2], sf[nt][3]));
        }
        mt0 = fmaxf(mt0, __shfl_xor_sync(0xffffffffu, mt0, 1));
        mt0 = fmaxf(mt0, __shfl_xor_sync(0xffffffffu, mt0, 2));
        mt1 = fmaxf(mt1, __shfl_xor_sync(0xffffffffu, mt1, 1));
        mt1 = fmaxf(mt1, __shfl_xor_sync(0xffffffffu, mt1, 2));

        const float mn0 = fmaxf(m0r, mt0), mn1 = fmaxf(m1r, mt1);
        const float a0s = __expf(m0r - mn0), a1s = __expf(m1r - mn1);
        m0r = mn0; m1r = mn1;

        float s0sum = 0.f, s1sum = 0.f;
        #pragma unroll
        for (int nt = 0; nt < 8; nt++) {
            float p0 = __expf(sf[nt][0] - mn0);
            float p1 = __expf(sf[nt][1] - mn0);
            float p2 = __expf(sf[nt][2] - mn1);
            float p3 = __expf(sf[nt][3] - mn1);
            s0sum += p0 + p1; s1sum += p2 + p3;
            __half2 hp0 = __floats2half2_rn(p0, p1);
            __half2 hp1 = __floats2half2_rn(p2, p3);
            Ps[(wrow + grp)     * K36 + nt*4 + tig] = __uint_as_float(*(uint32_t*)&hp0);
            Ps[(wrow + grp + 8) * K36 + nt*4 + tig] = __uint_as_float(*(uint32_t*)&hp1);
        }
        s0sum += __shfl_xor_sync(0xffffffffu, s0sum, 1);
        s0sum += __shfl_xor_sync(0xffffffffu, s0sum, 2);
        s1sum += __shfl_xor_sync(0xffffffffu, s1sum, 1);
        s1sum += __shfl_xor_sync(0xffffffffu, s1sum, 2);
        l0 = l0 * a0s + s0sum;
        l1 = l1 * a1s + s1sum;
        #pragma unroll
        for (int nt = 0; nt < 8; nt++) {
            of[nt][0] *= a0s; of[nt][1] *= a0s;
            of[nt][2] *= a1s; of[nt][3] *= a1s;
        }
        __syncwarp();

        #pragma unroll
        for (int ks = 0; ks < 4; ks++) {
            uint32_t ap[4];
            const uint32_t offP = (uint32_t)((wrow + a_row) * K36 + ks*8 + a_k) * 4u;
            ldm4(ap, aPs + offP);
            #pragma unroll
            for (int nt2 = 0; nt2 < 4; nt2++) {
                const uint32_t offV = (uint32_t)((nt2*16 + b_row) * K36 + ks*8 + b_k) * 4u;
                uint32_t rh[4], rl[4];
                ldm4(rh, aVthi + offV);
                ldm4(rl, aVtlo + offV);
                mma16(of[2*nt2],   ap, rh[0], rh[1]);
                mma16(of[2*nt2],   ap, rl[0], rl[1]);
                mma16(of[2*nt2+1], ap, rh[2], rh[3]);
                mma16(of[2*nt2+1], ap, rl[2], rl[3]);
            }
        }

        if (tt + 1 < ntiles) KV_STORE((tt + 1) & 1);
        __syncthreads();
    }
    #undef KV_STORE

    // epilogue: normalize; write concat as fp16 hi/lo planes
    const float inv0 = 1.0f / l0, inv1 = 1.0f / l1;
    const size_t ro0 = ((size_t)b * SS + s0 + wrow + grp) * DD + h * DKK;
    const size_t ro1 = ro0 + (size_t)8 * DD;
    #pragma unroll
    for (int nt = 0; nt < 8; nt++) {
        const int col = nt*8 + 2*tig;
        float v0 = of[nt][0] * inv0, v1 = of[nt][1] * inv0;
        __half2 hh0 = __floats2half2_rn(v0, v1);
        float2  ff0 = __half22float2(hh0);
        __half2 ll0 = __floats2half2_rn(v0 - ff0.x, v1 - ff0.y);
        *reinterpret_cast<__half2*>(och + ro0 + col) = hh0;
        *reinterpret_cast<__half2*>(ocl + ro0 + col) = ll0;
        float v2 = of[nt][2] * inv1, v3 = of[nt][3] * inv1;
        __half2 hh1 = __floats2half2_rn(v2, v3);
        float2  ff1 = __half22float2(hh1);
        __half2 ll1 = __floats2half2_rn(v2 - ff1.x, v3 - ff1.y);
        *reinterpret_cast<__half2*>(och + ro1 + col) = hh1;
        *reinterpret_cast<__half2*>(ocl + ro1 + col) = ll1;
    }
}

// ---------------------------------------------------------------------------
extern "C" void kernel_launch(void* const* d_in, const int* in_sizes, int n_in,
                              void* d_out, int out_size)
{
    const float* Q  = (const float*)d_in[0];
    const float* K  = (const float*)d_in[1];
    const float* V  = (const float*)d_in[2];
    // d_in[3] = causal mask (unused)
    const float* Wq = (const float*)d_in[4];
    const float* Wk = (const float*)d_in[5];
    const float* Wv = (const float*)d_in[6];
    const float* Wo = (const float*)d_in[7];
    const float* bo = (const float*)d_in[8];
    float* out = (float*)d_out;

    __half *wh, *wl, *xh, *xl, *ch, *cl;
    cudaGetSymbolAddress((void**)&wh, g_wh);
    cudaGetSymbolAddress((void**)&wl, g_wl);
    cudaGetSymbolAddress((void**)&xh, g_xh);
    cudaGetSymbolAddress((void**)&xl, g_xl);
    cudaGetSymbolAddress((void**)&ch, g_ch);
    cudaGetSymbolAddress((void**)&cl, g_cl);

    cudaFuncSetAttribute(gemm_fp16<0>, cudaFuncAttributeMaxDynamicSharedMemorySize, GEMM_SMEM);
    cudaFuncSetAttribute(gemm_fp16<1>, cudaFuncAttributeMaxDynamicSharedMemorySize, GEMM_SMEM);
    cudaFuncSetAttribute(attn_mma, cudaFuncAttributeMaxDynamicSharedMemorySize, ATTN_SMEM);

    const dim3 tg(DKK / 32, DD / 32, HH);     // (2, 32, 16)
    const int  nw8 = WSZ / 8;

    transpose_split_w<<<tg, 256>>>(Wq, wh, wl);
    transpose_split_w<<<tg, 256>>>(Wk, wh + WSZ, wl + WSZ);
    transpose_split_w<<<tg, 256>>>(Wv, wh + 2*WSZ, wl + 2*WSZ);
    split_half<<<nw8/256, 256>>>((const float4*)Wo, (uint4*)(wh + 3*WSZ), (uint4*)(wl + 3*WSZ), nw8);

    // fused Q/K/V projections -> fp16 hi/lo planes
    gemm_fp16<0><<<dim3(3 * DD / BN, NN / BM), 256, GEMM_SMEM>>>(
        Q, K, V, nullptr, nullptr, wh, wl, nullptr, nullptr, xh, xl);

    attn_mma<<<dim3(SS/TQ, HH, BB), 256, ATTN_SMEM>>>(
        xh, xl, xh + NND, xl + NND, xh + 2*NND, xl + 2*NND, ch, cl);

    // output projection: pre-split concat -> fp32 out (+bias)
    gemm_fp16<1><<<dim3(DD / BN, NN / BM), 256, GEMM_SMEM>>>(
        nullptr, nullptr, nullptr, ch, cl, wh + 3*WSZ, wl + 3*WSZ, bo, out, nullptr, nullptr);
}